// round 10
// baseline (speedup 1.0000x reference)
#include <cuda_runtime.h>
#include <cuda_bf16.h>
#include <math_constants.h>
#include <cstdint>

#define BB 4
#define CC 64
#define NN 16384
#define KK 16
#define CO 64

// ---------------- scratch globals (no allocation allowed) ----------------
__device__ float g_yT[BB*NN*CO];    // y transposed: [b*N+n][o]
__device__ float g_zT[BB*NN*CO];    // z transposed: [b*N+n][o]
__device__ float g_hmax[BB*NN*CO];  // max_k h = y - min_k z_e
__device__ float g_hmin[BB*NN*CO];  // min_k h = y - max_k z_e
__device__ float g_sum[CO];
__device__ float g_sumsq[CO];
__device__ float g_scale[CO];
__device__ float g_shift[CO];
__device__ int   g_ticket;

__device__ __forceinline__ uint32_t smem_u32(const void* p) {
    uint32_t a;
    asm("{ .reg .u64 t; cvta.to.shared.u64 t, %1; cvt.u32.u64 %0, t; }" : "=r"(a) : "l"(p));
    return a;
}

__device__ __forceinline__ uint32_t pack_hi(float v0, float v1, float& l0, float& l1) {
    __nv_bfloat162 h2 = __floats2bfloat162_rn(v0, v1);
    l0 = v0 - __bfloat162float(h2.x);
    l1 = v1 - __bfloat162float(h2.y);
    return ((uint32_t)__bfloat16_as_ushort(h2.y) << 16) | __bfloat16_as_ushort(h2.x);
}
__device__ __forceinline__ uint32_t pack_lo(float l0, float l1) {
    __nv_bfloat162 l2 = __floats2bfloat162_rn(l0, l1);
    return ((uint32_t)__bfloat16_as_ushort(l2.y) << 16) | __bfloat16_as_ushort(l2.x);
}

#define LDSM_X4(r0, r1, r2, r3, addr)                                          \
    asm volatile("ldmatrix.sync.aligned.m8n8.x4.shared.b16 {%0,%1,%2,%3}, [%4];" \
        : "=r"(r0), "=r"(r1), "=r"(r2), "=r"(r3) : "r"(addr))

#define MMA16816(acc, a0, a1, a2, a3, b0, b1)                                  \
    asm volatile("mma.sync.aligned.m16n8k16.row.col.f32.bf16.bf16.f32 "        \
        "{%0,%1,%2,%3},{%4,%5,%6,%7},{%8,%9},{%0,%1,%2,%3};"                   \
        : "+f"((acc)[0]), "+f"((acc)[1]), "+f"((acc)[2]), "+f"((acc)[3])       \
        : "r"(a0), "r"(a1), "r"(a2), "r"(a3), "r"(b0), "r"(b1))

// Rows of 128B (64 bf16). 16B-chunk XOR swizzle: chunk ch of row r lives at
// (ch ^ (r&7)). ldmatrix 8-lane phases (8 consecutive rows, same ch) hit 8
// distinct 16B banks -> conflict-free. u32 index for pair p (2 channels):
#define SIDX(r, p) ((r)*32 + (((p) >> 2) ^ ((r)&7))*4 + ((p)&3))

// ---------------------------------------------------------------------------
// Kernel A: dual GEMM via m16n8k16 bf16 + ldmatrix.x4. Block = 128 thr
// (4 warps), tile = 64 n-rows x 128 out-rows (ws:0-63 -> yT, w2:64-127 -> zT).
// K=64 fp32 split bf16 hi/lo, 3 compensation passes (xh*wh + xl*wh + xh*wl).
// Smem = 48KB static exactly. Block 0 resets stats accumulators.
// ---------------------------------------------------------------------------
__global__ void __launch_bounds__(128) k_gemm(const float* __restrict__ x,
                                              const float* __restrict__ W) {
    __shared__ uint32_t Ah[64*32];    // 8KB
    __shared__ uint32_t Al[64*32];    // 8KB
    __shared__ uint32_t Bh[128*32];   // 16KB (rows 0-63 ws, 64-127 w2)
    __shared__ uint32_t Bl[128*32];   // 16KB

    int tid  = threadIdx.x;
    int w    = tid >> 5;
    int lane = tid & 31;
    int g    = lane >> 2;
    int t4   = lane & 3;

    if (blockIdx.x == 0) {
        if (tid < CO) { g_sum[tid] = 0.f; g_sumsq[tid] = 0.f; }
        if (tid == 0) g_ticket = 0;
    }

    int bn0  = blockIdx.x * 64;
    int b    = bn0 >> 14;
    int nloc = bn0 & (NN - 1);
    const float* xb = x + ((size_t)b << 20) + nloc;

    // ---- fill A (x[c][n] -> A[n][c] bf16 hi/lo) ----
    for (int i = tid; i < 64*32; i += 128) {
        int n = i & 63, p = i >> 6;
        float v0 = xb[(size_t)(2*p)   * NN + n];
        float v1 = xb[(size_t)(2*p+1) * NN + n];
        float l0, l1;
        uint32_t hp = pack_hi(v0, v1, l0, l1);
        int idx = SIDX(n, p);
        Ah[idx] = hp;
        Al[idx] = pack_lo(l0, l1);
    }
    // ---- fill B: ws = W1+W2 (rows 0-63), w2 = W2 (rows 64-127) ----
    for (int i = tid; i < 64*32; i += 128) {
        int j = i >> 5, p = i & 31;
        float w2a = W[j*128 + 64 + 2*p];
        float w2b = W[j*128 + 64 + 2*p + 1];
        float wsa = W[j*128 + 2*p]     + w2a;
        float wsb = W[j*128 + 2*p + 1] + w2b;
        float l0, l1;
        int iy = SIDX(j, p);
        int iz = SIDX(j + 64, p);      // (j+64)&7 == j&7
        uint32_t hp = pack_hi(wsa, wsb, l0, l1);
        Bh[iy] = hp;  Bl[iy] = pack_lo(l0, l1);
        hp = pack_hi(w2a, w2b, l0, l1);
        Bh[iz] = hp;  Bl[iz] = pack_lo(l0, l1);
    }
    __syncthreads();

    // ---- per-lane ldmatrix address prep ----
    int m0   = w * 16;
    int aRow = m0 + (lane & 15);
    uint32_t aCo = (uint32_t)(lane >> 4);         // chunk parity
    uint32_t a_r7 = (uint32_t)(aRow & 7);
    uint32_t aOff = (uint32_t)aRow * 128;
    uint32_t AhB = smem_u32(Ah) + aOff;
    uint32_t AlB = smem_u32(Al) + aOff;

    int bRowL = ((lane >> 4) << 3) + (lane & 7);  // 0..15 within ct-pair
    uint32_t bCo = (uint32_t)((lane >> 3) & 1);
    uint32_t b_r7 = (uint32_t)(lane & 7);
    uint32_t BhBase = smem_u32(Bh);
    uint32_t BlBase = smem_u32(Bl);
    uint32_t bOff[4];
    #pragma unroll
    for (int ctp = 0; ctp < 4; ctp++)
        bOff[ctp] = (uint32_t)(ctp*16 + bRowL) * 128;

    float accY[8][4], accZ[8][4];
    #pragma unroll
    for (int ct = 0; ct < 8; ct++)
        #pragma unroll
        for (int q = 0; q < 4; q++) { accY[ct][q] = 0.f; accZ[ct][q] = 0.f; }

    #pragma unroll
    for (int pass = 0; pass < 3; pass++) {
        uint32_t Asel = (pass == 1) ? AlB : AhB;
        uint32_t Bsel = (pass == 2) ? BlBase : BhBase;
        #pragma unroll
        for (int ks = 0; ks < 4; ks++) {
            uint32_t a0, a1, a2, a3;
            uint32_t ach = (((uint32_t)(2*ks) + aCo) ^ a_r7) << 4;
            LDSM_X4(a0, a1, a2, a3, Asel + ach);
            uint32_t bch = (((uint32_t)(2*ks) + bCo) ^ b_r7) << 4;
            #pragma unroll
            for (int ctp = 0; ctp < 4; ctp++) {
                uint32_t by = Bsel + bOff[ctp] + bch;
                uint32_t b0, b1, b2, b3;
                LDSM_X4(b0, b1, b2, b3, by);
                MMA16816(accY[2*ctp],   a0, a1, a2, a3, b0, b1);
                MMA16816(accY[2*ctp+1], a0, a1, a2, a3, b2, b3);
                LDSM_X4(b0, b1, b2, b3, by + 64*128);
                MMA16816(accZ[2*ctp],   a0, a1, a2, a3, b0, b1);
                MMA16816(accZ[2*ctp+1], a0, a1, a2, a3, b2, b3);
            }
        }
    }

    // ---- store: lane(g,t4) holds cols ct*8+2t4(+1), rows m0+g and m0+g+8 ----
    size_t r0 = (size_t)(bn0 + m0 + g) * CO;
    size_t r1 = r0 + 8*CO;
    #pragma unroll
    for (int ct = 0; ct < 8; ct++) {
        int o = ct*8 + 2*t4;
        *(float2*)&g_yT[r0 + o] = make_float2(accY[ct][0], accY[ct][1]);
        *(float2*)&g_yT[r1 + o] = make_float2(accY[ct][2], accY[ct][3]);
        *(float2*)&g_zT[r0 + o] = make_float2(accZ[ct][0], accZ[ct][1]);
        *(float2*)&g_zT[r1 + o] = make_float2(accZ[ct][2], accZ[ct][3]);
    }
}

// ---------------------------------------------------------------------------
// Kernel B: neighbor gather + stats (last block computes BN affine params).
// ---------------------------------------------------------------------------
__global__ void __launch_bounds__(256) k_gather(const int* __restrict__ edge,
                                                const float* __restrict__ gamma,
                                                const float* __restrict__ beta) {
    __shared__ float shsum[CO], shq[CO];
    __shared__ int s_last;
    int tid = threadIdx.x;
    int lane = tid & 31;
    int w = tid >> 5;
    if (tid < CO) { shsum[tid] = 0.f; shq[tid] = 0.f; }

    int bn0 = blockIdx.x * 64;
    int b = bn0 / NN;
    size_t zb = (size_t)b*NN*CO;

    float accs0 = 0.f, accs1 = 0.f, accq0 = 0.f, accq1 = 0.f;

    for (int it = 0; it < 8; it++) {
        int bn = bn0 + w*8 + it;
        size_t base = (size_t)bn*CO;
        float y0 = g_yT[base + lane];
        float y1 = g_yT[base + lane + 32];
        int myidx = edge[bn*KK + (lane & 15)];
        float s10 = 0.f, s11 = 0.f, q0 = 0.f, q1 = 0.f;
        float mn0 = CUDART_INF_F, mn1 = CUDART_INF_F;
        float mx0 = -CUDART_INF_F, mx1 = -CUDART_INF_F;
        #pragma unroll
        for (int k = 0; k < KK; k++) {
            int e = __shfl_sync(0xffffffffu, myidx, k);
            size_t zr = zb + (size_t)e*CO;
            float z0 = g_zT[zr + lane];
            float z1 = g_zT[zr + lane + 32];
            s10 += z0; q0 = fmaf(z0, z0, q0);
            mn0 = fminf(mn0, z0); mx0 = fmaxf(mx0, z0);
            s11 += z1; q1 = fmaf(z1, z1, q1);
            mn1 = fminf(mn1, z1); mx1 = fmaxf(mx1, z1);
        }
        g_hmax[base + lane]      = y0 - mn0;
        g_hmax[base + lane + 32] = y1 - mn1;
        g_hmin[base + lane]      = y0 - mx0;
        g_hmin[base + lane + 32] = y1 - mx1;
        accs0 += (float)KK*y0 - s10;
        accs1 += (float)KK*y1 - s11;
        accq0 += fmaf((float)KK*y0, y0, fmaf(-2.f*y0, s10, q0));
        accq1 += fmaf((float)KK*y1, y1, fmaf(-2.f*y1, s11, q1));
    }
    __syncthreads();
    atomicAdd(&shsum[lane],      accs0);
    atomicAdd(&shsum[lane + 32], accs1);
    atomicAdd(&shq[lane],        accq0);
    atomicAdd(&shq[lane + 32],   accq1);
    __syncthreads();
    if (tid < CO) {
        atomicAdd(&g_sum[tid],   shsum[tid]);
        atomicAdd(&g_sumsq[tid], shq[tid]);
    }
    __threadfence();
    __syncthreads();
    if (tid == 0) s_last = (atomicAdd(&g_ticket, 1) == (int)gridDim.x - 1);
    __syncthreads();
    if (s_last && tid < CO) {
        const float inv = 1.0f / (float)((long long)BB*NN*KK);
        float sm = atomicAdd(&g_sum[tid],   0.f);
        float sq = atomicAdd(&g_sumsq[tid], 0.f);
        float mean = sm * inv;
        float var  = sq * inv - mean*mean;
        float s = gamma[tid] * rsqrtf(var + 1e-5f);
        g_scale[tid] = s;
        g_shift[tid] = beta[tid] - mean * s;
    }
}

// ---------------------------------------------------------------------------
// Kernel C: epilogue + transpose to output layout (B, CO, N).
// max_k leaky(s*h+t) = leaky(s*hext + t), hext = hmax if s>=0 else hmin.
// ---------------------------------------------------------------------------
__global__ void __launch_bounds__(256) k_out(float* __restrict__ out) {
    __shared__ float tile[64*65];
    __shared__ float ss[CO], tt[CO];
    int tid = threadIdx.x;
    if (tid < CO) { ss[tid] = g_scale[tid]; tt[tid] = g_shift[tid]; }
    __syncthreads();
    int b = blockIdx.y;
    int n0 = blockIdx.x * 64;
    size_t base = ((size_t)b*NN + n0)*CO;
    for (int i = tid; i < 64*64; i += 256) {
        int nl = i >> 6, o = i & 63;
        float s = ss[o];
        const float* src = (s >= 0.f) ? g_hmax : g_hmin;
        float v = src[base + (size_t)nl*CO + o];
        float h = fmaf(s, v, tt[o]);
        tile[o*65 + nl] = (h >= 0.f) ? h : 0.2f*h;
    }
    __syncthreads();
    size_t ob = (size_t)b*CO*NN + n0;
    for (int i = tid; i < 64*64; i += 256) {
        int o = i >> 6, nl = i & 63;
        out[ob + (size_t)o*NN + nl] = tile[o*65 + nl];
    }
}

extern "C" void kernel_launch(void* const* d_in, const int* in_sizes, int n_in,
                              void* d_out, int out_size) {
    const float* x     = (const float*)d_in[0];
    const int*   edge  = (const int*)d_in[1];
    const float* W     = (const float*)d_in[2];
    const float* gamma = (const float*)d_in[3];
    const float* beta  = (const float*)d_in[4];
    float* out = (float*)d_out;

    k_gemm<<<BB*NN/64, 128>>>(x, W);
    k_gather<<<BB*NN/64, 256>>>(edge, gamma, beta);
    k_out<<<dim3(NN/64, BB), 256>>>(out);
}

// round 12
// speedup vs baseline: 1.1246x; 1.1246x over previous
#include <cuda_runtime.h>
#include <cuda_bf16.h>
#include <math_constants.h>
#include <cstdint>

#define BB 4
#define CC 64
#define NN 16384
#define KK 16
#define CO 64

// ---------------- scratch globals (no allocation allowed) ----------------
__device__ float g_yT[BB*NN*CO];    // y transposed: [b*N+n][o]
__device__ float g_zT[BB*NN*CO];    // z transposed: [b*N+n][o]
__device__ float g_hmax[BB*NN*CO];  // max_k h = y - min_k z_e
__device__ float g_hmin[BB*NN*CO];  // min_k h = y - max_k z_e
__device__ float g_sum[CO];
__device__ float g_sumsq[CO];
__device__ float g_scale[CO];
__device__ float g_shift[CO];
__device__ int   g_ticket;

__device__ __forceinline__ uint32_t smem_u32(const void* p) {
    uint32_t a;
    asm("{ .reg .u64 t; cvta.to.shared.u64 t, %1; cvt.u32.u64 %0, t; }" : "=r"(a) : "l"(p));
    return a;
}

__device__ __forceinline__ uint32_t pack_hi(float v0, float v1, float& l0, float& l1) {
    __nv_bfloat162 h2 = __floats2bfloat162_rn(v0, v1);
    l0 = v0 - __bfloat162float(h2.x);
    l1 = v1 - __bfloat162float(h2.y);
    return ((uint32_t)__bfloat16_as_ushort(h2.y) << 16) | __bfloat16_as_ushort(h2.x);
}
__device__ __forceinline__ uint32_t pack_lo(float l0, float l1) {
    __nv_bfloat162 l2 = __floats2bfloat162_rn(l0, l1);
    return ((uint32_t)__bfloat16_as_ushort(l2.y) << 16) | __bfloat16_as_ushort(l2.x);
}

#define LDSM_X4(r0, r1, r2, r3, addr)                                          \
    asm volatile("ldmatrix.sync.aligned.m8n8.x4.shared.b16 {%0,%1,%2,%3}, [%4];" \
        : "=r"(r0), "=r"(r1), "=r"(r2), "=r"(r3) : "r"(addr))

#define MMA16816(acc, a0, a1, a2, a3, b0, b1)                                  \
    asm volatile("mma.sync.aligned.m16n8k16.row.col.f32.bf16.bf16.f32 "        \
        "{%0,%1,%2,%3},{%4,%5,%6,%7},{%8,%9},{%0,%1,%2,%3};"                   \
        : "+f"((acc)[0]), "+f"((acc)[1]), "+f"((acc)[2]), "+f"((acc)[3])       \
        : "r"(a0), "r"(a1), "r"(a2), "r"(a3), "r"(b0), "r"(b1))

// Rows of 128B (64 bf16). 16B-chunk XOR swizzle: chunk ch of row r lives at
// (ch ^ (r&7)); ldmatrix 8-lane phases hit 8 distinct 16B banks.
#define SIDX(r, p) ((r)*32 + (((p) >> 2) ^ ((r)&7))*4 + ((p)&3))

// ---------------------------------------------------------------------------
// Kernel A: GEMM via m16n8k16 bf16 + ldmatrix.x4, R4 tiling. Block = 256 thr
// (8 warps), tile = 128 n-rows x 64 out-cols, two B matrices (ws=W1+W2 -> yT,
// w2=W2 -> zT) back-to-back reusing B smem. K=64 fp32 split bf16 hi/lo,
// 3 compensation passes (xh*wh + xl*wh + xh*wl). Smem = 48KB static.
// Block 0 resets stats accumulators.
// ---------------------------------------------------------------------------
__global__ void __launch_bounds__(256) k_gemm(const float* __restrict__ x,
                                              const float* __restrict__ W) {
    __shared__ uint32_t Ah[128*32];   // 16KB
    __shared__ uint32_t Al[128*32];   // 16KB
    __shared__ uint32_t Bh[64*32];    // 8KB
    __shared__ uint32_t Bl[64*32];    // 8KB

    int tid  = threadIdx.x;
    int w    = tid >> 5;
    int lane = tid & 31;
    int g    = lane >> 2;
    int t4   = lane & 3;

    if (blockIdx.x == 0) {
        if (tid < CO) { g_sum[tid] = 0.f; g_sumsq[tid] = 0.f; }
        if (tid == 0) g_ticket = 0;
    }

    int bn0  = blockIdx.x * 128;
    int b    = bn0 >> 14;
    int nloc = bn0 & (NN - 1);
    const float* xb = x + ((size_t)b << 20) + nloc;

    // ---- fill A (x[c][n] -> A[n][c] bf16 hi/lo, swizzled) ----
    for (int i = tid; i < 128*32; i += 256) {
        int n = i & 127, p = i >> 7;            // consecutive tid -> n: coalesced
        float v0 = xb[(size_t)(2*p)   * NN + n];
        float v1 = xb[(size_t)(2*p+1) * NN + n];
        float l0, l1;
        uint32_t hp = pack_hi(v0, v1, l0, l1);
        int idx = SIDX(n, p);
        Ah[idx] = hp;
        Al[idx] = pack_lo(l0, l1);
    }

    // ---- per-lane ldmatrix address prep ----
    int m0   = w * 16;
    int aRow = m0 + (lane & 15);
    uint32_t aCo  = (uint32_t)(lane >> 4);
    uint32_t a_r7 = (uint32_t)(aRow & 7);
    uint32_t AhB = smem_u32(Ah) + (uint32_t)aRow * 128;
    uint32_t AlB = smem_u32(Al) + (uint32_t)aRow * 128;

    int bRowL = ((lane >> 4) << 3) + (lane & 7);   // 0..15 within ct-pair
    uint32_t bCo  = (uint32_t)((lane >> 3) & 1);
    uint32_t b_r7 = (uint32_t)(lane & 7);
    uint32_t BhBase = smem_u32(Bh);
    uint32_t BlBase = smem_u32(Bl);
    uint32_t bOff[4];
    #pragma unroll
    for (int ctp = 0; ctp < 4; ctp++)
        bOff[ctp] = (uint32_t)(ctp*16 + bRowL) * 128;

    float acc[8][4];

    #pragma unroll 1
    for (int mat = 0; mat < 2; mat++) {
        __syncthreads();   // mat 1: all warps done reading old B
        // ---- fill B for this matrix ----
        for (int i = tid; i < 64*32; i += 256) {
            int j = i >> 5, p = i & 31;
            float v0, v1;
            if (mat == 0) {
                v0 = W[j*128 + 2*p]     + W[j*128 + 64 + 2*p];
                v1 = W[j*128 + 2*p + 1] + W[j*128 + 64 + 2*p + 1];
            } else {
                v0 = W[j*128 + 64 + 2*p];
                v1 = W[j*128 + 64 + 2*p + 1];
            }
            float l0, l1;
            uint32_t hp = pack_hi(v0, v1, l0, l1);
            int idx = SIDX(j, p);
            Bh[idx] = hp;
            Bl[idx] = pack_lo(l0, l1);
        }
        __syncthreads();

        #pragma unroll
        for (int ct = 0; ct < 8; ct++)
            #pragma unroll
            for (int q = 0; q < 4; q++) acc[ct][q] = 0.f;

        // ---- 3 compensation passes x 4 k-steps ----
        #pragma unroll
        for (int pass = 0; pass < 3; pass++) {
            uint32_t Asel = (pass == 1) ? AlB : AhB;
            uint32_t Bsel = (pass == 2) ? BlBase : BhBase;
            #pragma unroll
            for (int ks = 0; ks < 4; ks++) {
                uint32_t a0, a1, a2, a3;
                uint32_t ach = (((uint32_t)(2*ks) + aCo) ^ a_r7) << 4;
                LDSM_X4(a0, a1, a2, a3, Asel + ach);
                uint32_t bch = (((uint32_t)(2*ks) + bCo) ^ b_r7) << 4;
                #pragma unroll
                for (int ctp = 0; ctp < 4; ctp++) {
                    uint32_t b0, b1, b2, b3;
                    LDSM_X4(b0, b1, b2, b3, Bsel + bOff[ctp] + bch);
                    MMA16816(acc[2*ctp],   a0, a1, a2, a3, b0, b1);
                    MMA16816(acc[2*ctp+1], a0, a1, a2, a3, b2, b3);
                }
            }
        }

        // ---- store: lane(g,t4) holds cols ct*8+2t4(+1), rows m0+g, m0+g+8 ----
        float* dst = (mat == 0) ? g_yT : g_zT;
        size_t r0 = (size_t)(bn0 + m0 + g) * CO;
        size_t r1 = r0 + 8*CO;
        #pragma unroll
        for (int ct = 0; ct < 8; ct++) {
            int o = ct*8 + 2*t4;
            *(float2*)&dst[r0 + o] = make_float2(acc[ct][0], acc[ct][1]);
            *(float2*)&dst[r1 + o] = make_float2(acc[ct][2], acc[ct][3]);
        }
    }
}

// ---------------------------------------------------------------------------
// Kernel B: neighbor gather + stats (last block computes BN affine params).
// ---------------------------------------------------------------------------
__global__ void __launch_bounds__(256) k_gather(const int* __restrict__ edge,
                                                const float* __restrict__ gamma,
                                                const float* __restrict__ beta) {
    __shared__ float shsum[CO], shq[CO];
    __shared__ int s_last;
    int tid = threadIdx.x;
    int lane = tid & 31;
    int w = tid >> 5;
    if (tid < CO) { shsum[tid] = 0.f; shq[tid] = 0.f; }

    int bn0 = blockIdx.x * 64;
    int b = bn0 / NN;
    size_t zb = (size_t)b*NN*CO;

    float accs0 = 0.f, accs1 = 0.f, accq0 = 0.f, accq1 = 0.f;

    for (int it = 0; it < 8; it++) {
        int bn = bn0 + w*8 + it;
        size_t base = (size_t)bn*CO;
        float y0 = g_yT[base + lane];
        float y1 = g_yT[base + lane + 32];
        int myidx = edge[bn*KK + (lane & 15)];
        float s10 = 0.f, s11 = 0.f, q0 = 0.f, q1 = 0.f;
        float mn0 = CUDART_INF_F, mn1 = CUDART_INF_F;
        float mx0 = -CUDART_INF_F, mx1 = -CUDART_INF_F;
        #pragma unroll
        for (int k = 0; k < KK; k++) {
            int e = __shfl_sync(0xffffffffu, myidx, k);
            size_t zr = zb + (size_t)e*CO;
            float z0 = g_zT[zr + lane];
            float z1 = g_zT[zr + lane + 32];
            s10 += z0; q0 = fmaf(z0, z0, q0);
            mn0 = fminf(mn0, z0); mx0 = fmaxf(mx0, z0);
            s11 += z1; q1 = fmaf(z1, z1, q1);
            mn1 = fminf(mn1, z1); mx1 = fmaxf(mx1, z1);
        }
        g_hmax[base + lane]      = y0 - mn0;
        g_hmax[base + lane + 32] = y1 - mn1;
        g_hmin[base + lane]      = y0 - mx0;
        g_hmin[base + lane + 32] = y1 - mx1;
        accs0 += (float)KK*y0 - s10;
        accs1 += (float)KK*y1 - s11;
        accq0 += fmaf((float)KK*y0, y0, fmaf(-2.f*y0, s10, q0));
        accq1 += fmaf((float)KK*y1, y1, fmaf(-2.f*y1, s11, q1));
    }
    __syncthreads();
    atomicAdd(&shsum[lane],      accs0);
    atomicAdd(&shsum[lane + 32], accs1);
    atomicAdd(&shq[lane],        accq0);
    atomicAdd(&shq[lane + 32],   accq1);
    __syncthreads();
    if (tid < CO) {
        atomicAdd(&g_sum[tid],   shsum[tid]);
        atomicAdd(&g_sumsq[tid], shq[tid]);
    }
    __threadfence();
    __syncthreads();
    if (tid == 0) s_last = (atomicAdd(&g_ticket, 1) == (int)gridDim.x - 1);
    __syncthreads();
    if (s_last && tid < CO) {
        const float inv = 1.0f / (float)((long long)BB*NN*KK);
        float sm = atomicAdd(&g_sum[tid],   0.f);
        float sq = atomicAdd(&g_sumsq[tid], 0.f);
        float mean = sm * inv;
        float var  = sq * inv - mean*mean;
        float s = gamma[tid] * rsqrtf(var + 1e-5f);
        g_scale[tid] = s;
        g_shift[tid] = beta[tid] - mean * s;
    }
}

// ---------------------------------------------------------------------------
// Kernel C: epilogue + transpose to output layout (B, CO, N).
// max_k leaky(s*h+t) = leaky(s*hext + t), hext = hmax if s>=0 else hmin.
// ---------------------------------------------------------------------------
__global__ void __launch_bounds__(256) k_out(float* __restrict__ out) {
    __shared__ float tile[64*65];
    __shared__ float ss[CO], tt[CO];
    int tid = threadIdx.x;
    if (tid < CO) { ss[tid] = g_scale[tid]; tt[tid] = g_shift[tid]; }
    __syncthreads();
    int b = blockIdx.y;
    int n0 = blockIdx.x * 64;
    size_t base = ((size_t)b*NN + n0)*CO;
    for (int i = tid; i < 64*64; i += 256) {
        int nl = i >> 6, o = i & 63;
        float s = ss[o];
        const float* src = (s >= 0.f) ? g_hmax : g_hmin;
        float v = src[base + (size_t)nl*CO + o];
        float h = fmaf(s, v, tt[o]);
        tile[o*65 + nl] = (h >= 0.f) ? h : 0.2f*h;
    }
    __syncthreads();
    size_t ob = (size_t)b*CO*NN + n0;
    for (int i = tid; i < 64*64; i += 256) {
        int o = i >> 6, nl = i & 63;
        out[ob + (size_t)o*NN + nl] = tile[o*65 + nl];
    }
}

extern "C" void kernel_launch(void* const* d_in, const int* in_sizes, int n_in,
                              void* d_out, int out_size) {
    const float* x     = (const float*)d_in[0];
    const int*   edge  = (const int*)d_in[1];
    const float* W     = (const float*)d_in[2];
    const float* gamma = (const float*)d_in[3];
    const float* beta  = (const float*)d_in[4];
    float* out = (float*)d_out;

    k_gemm<<<BB*NN/128, 256>>>(x, W);
    k_gather<<<BB*NN/64, 256>>>(edge, gamma, beta);
    k_out<<<dim3(NN/64, BB), 256>>>(out);
}

// round 15
// speedup vs baseline: 1.1744x; 1.0443x over previous
#include <cuda_runtime.h>
#include <cuda_fp16.h>
#include <math_constants.h>
#include <cstdint>

#define BB 4
#define CC 64
#define NN 16384
#define KK 16
#define CO 64

// ---------------- scratch globals (no allocation allowed) ----------------
__device__ float g_yT[BB*NN*CO];    // y transposed: [b*N+n][o]
__device__ float g_zT[BB*NN*CO];    // z transposed: [b*N+n][o]
__device__ float g_hmax[BB*NN*CO];  // max_k h = y - min_k z_e
__device__ float g_hmin[BB*NN*CO];  // min_k h = y - max_k z_e
__device__ float g_sum[CO];
__device__ float g_sumsq[CO];
__device__ float g_scale[CO];
__device__ float g_shift[CO];
__device__ int   g_ticket;

__device__ __forceinline__ uint32_t smem_u32(const void* p) {
    uint32_t a;
    asm("{ .reg .u64 t; cvta.to.shared.u64 t, %1; cvt.u32.u64 %0, t; }" : "=r"(a) : "l"(p));
    return a;
}

// fp16 hi/lo split helpers (x = hi + lo exactly captures 21+ mantissa bits)
__device__ __forceinline__ uint32_t hpack(float v0, float v1) {
    __half2 h2 = __floats2half2_rn(v0, v1);
    return *reinterpret_cast<uint32_t*>(&h2);
}
__device__ __forceinline__ uint32_t hpack_hi(float v0, float v1, float& l0, float& l1) {
    __half2 h2 = __floats2half2_rn(v0, v1);
    l0 = v0 - __half2float(__low2half(h2));
    l1 = v1 - __half2float(__high2half(h2));
    return *reinterpret_cast<uint32_t*>(&h2);
}

#define LDSM_X4(r0, r1, r2, r3, addr)                                          \
    asm volatile("ldmatrix.sync.aligned.m8n8.x4.shared.b16 {%0,%1,%2,%3}, [%4];" \
        : "=r"(r0), "=r"(r1), "=r"(r2), "=r"(r3) : "r"(addr))

#define MMA16816H(acc, a0, a1, a2, a3, b0, b1)                                 \
    asm volatile("mma.sync.aligned.m16n8k16.row.col.f32.f16.f16.f32 "          \
        "{%0,%1,%2,%3},{%4,%5,%6,%7},{%8,%9},{%0,%1,%2,%3};"                   \
        : "+f"((acc)[0]), "+f"((acc)[1]), "+f"((acc)[2]), "+f"((acc)[3])       \
        : "r"(a0), "r"(a1), "r"(a2), "r"(a3), "r"(b0), "r"(b1))

// Rows of 128B (64 fp16). 16B-chunk XOR swizzle: chunk ch of row r lives at
// (ch ^ (r&7)); ldmatrix 8-lane phases hit 8 distinct 16B banks.
#define SIDX(r, p) ((r)*32 + (((p) >> 2) ^ ((r)&7))*4 + ((p)&3))

// ---------------------------------------------------------------------------
// Kernel A: dual GEMM, fp16 2-pass compensation (exact GEMM with W'=fp16(W)):
//   x = xh + xl (both fp16, exact);  result = xh*Wh + xl*Wh.
// Block = 256 thr / 8 warps. Tile = 64 n-rows x 128 out-rows (B combined:
// rows 0-63 = W1+W2 -> yT via warps 0-3, rows 64-127 = W2 -> zT via warps
// 4-7). B fragments hoisted out of the pass loop (pass-invariant).
// Smem = 32KB; launch_bounds(256,3) -> 3 blocks/SM.
// ---------------------------------------------------------------------------
__global__ void __launch_bounds__(256, 3) k_gemm(const float* __restrict__ x,
                                                 const float* __restrict__ W) {
    __shared__ uint32_t Ah[64*32];    // 8KB  (x hi, fp16x2)
    __shared__ uint32_t Al[64*32];    // 8KB  (x lo)
    __shared__ uint32_t Bh[128*32];   // 16KB (fp16(ws) rows 0-63, fp16(w2) rows 64-127)

    int tid  = threadIdx.x;
    int w    = tid >> 5;
    int lane = tid & 31;
    int g    = lane >> 2;
    int t4   = lane & 3;

    if (blockIdx.x == 0) {
        if (tid < CO) { g_sum[tid] = 0.f; g_sumsq[tid] = 0.f; }
        if (tid == 0) g_ticket = 0;
    }

    int bn0  = blockIdx.x * 64;
    int b    = bn0 >> 14;
    int nloc = bn0 & (NN - 1);
    const float* xb = x + ((size_t)b << 20) + nloc;

    // ---- fill A (x[c][n] -> A[n][c] fp16 hi/lo, swizzled) ----
    for (int i = tid; i < 64*32; i += 256) {
        int n = i & 63, p = i >> 6;
        float v0 = xb[(size_t)(2*p)   * NN + n];
        float v1 = xb[(size_t)(2*p+1) * NN + n];
        float l0, l1;
        uint32_t hp = hpack_hi(v0, v1, l0, l1);
        int idx = SIDX(n, p);
        Ah[idx] = hp;
        Al[idx] = hpack(l0, l1);
    }
    // ---- fill B: rows 0-63 ws=W1+W2, rows 64-127 w2=W2 (fp16 hi only) ----
    for (int i = tid; i < 128*32; i += 256) {
        int j = i >> 5, p = i & 31;
        float v0, v1;
        if (j < 64) {
            v0 = W[j*128 + 2*p]     + W[j*128 + 64 + 2*p];
            v1 = W[j*128 + 2*p + 1] + W[j*128 + 64 + 2*p + 1];
        } else {
            v0 = W[(j-64)*128 + 64 + 2*p];
            v1 = W[(j-64)*128 + 64 + 2*p + 1];
        }
        Bh[SIDX(j, p)] = hpack(v0, v1);
    }
    __syncthreads();

    // ---- per-lane ldmatrix address prep ----
    int m0   = (w & 3) * 16;                      // warps w and w+4 share rows
    int aRow = m0 + (lane & 15);
    uint32_t aCo  = (uint32_t)(lane >> 4);
    uint32_t a_r7 = (uint32_t)(aRow & 7);
    uint32_t AhB = smem_u32(Ah) + (uint32_t)aRow * 128;
    uint32_t AlB = smem_u32(Al) + (uint32_t)aRow * 128;

    int bHalf = (w >> 2) & 1;                     // 0: ws (yT), 1: w2 (zT)
    int bRowL = ((lane >> 4) << 3) + (lane & 7);
    uint32_t bCo  = (uint32_t)((lane >> 3) & 1);
    uint32_t b_r7 = (uint32_t)(lane & 7);
    uint32_t BhBase = smem_u32(Bh);
    uint32_t bOff[4];
    #pragma unroll
    for (int ctp = 0; ctp < 4; ctp++)
        bOff[ctp] = (uint32_t)(bHalf*64 + ctp*16 + bRowL) * 128;

    float acc[8][4];
    #pragma unroll
    for (int ct = 0; ct < 8; ct++)
        #pragma unroll
        for (int q = 0; q < 4; q++) acc[ct][q] = 0.f;

    // ---- 4 k-steps; B frags loaded once per ks, reused by both passes ----
    #pragma unroll
    for (int ks = 0; ks < 4; ks++) {
        uint32_t bf[4][4];
        uint32_t bch = (((uint32_t)(2*ks) + bCo) ^ b_r7) << 4;
        #pragma unroll
        for (int ctp = 0; ctp < 4; ctp++)
            LDSM_X4(bf[ctp][0], bf[ctp][1], bf[ctp][2], bf[ctp][3],
                    BhBase + bOff[ctp] + bch);
        uint32_t ach = (((uint32_t)(2*ks) + aCo) ^ a_r7) << 4;
        #pragma unroll
        for (int pass = 0; pass < 2; pass++) {
            uint32_t a0, a1, a2, a3;
            LDSM_X4(a0, a1, a2, a3, (pass ? AlB : AhB) + ach);
            #pragma unroll
            for (int ctp = 0; ctp < 4; ctp++) {
                MMA16816H(acc[2*ctp],   a0, a1, a2, a3, bf[ctp][0], bf[ctp][1]);
                MMA16816H(acc[2*ctp+1], a0, a1, a2, a3, bf[ctp][2], bf[ctp][3]);
            }
        }
    }

    // ---- store: warps 0-3 -> yT, warps 4-7 -> zT ----
    float* dst = bHalf ? g_zT : g_yT;
    size_t r0 = (size_t)(bn0 + m0 + g) * CO;
    size_t r1 = r0 + 8*CO;
    #pragma unroll
    for (int ct = 0; ct < 8; ct++) {
        int o = ct*8 + 2*t4;
        *(float2*)&dst[r0 + o] = make_float2(acc[ct][0], acc[ct][1]);
        *(float2*)&dst[r1 + o] = make_float2(acc[ct][2], acc[ct][3]);
    }
}

// ---------------------------------------------------------------------------
// Kernel B: neighbor gather + stats (last block computes BN affine params).
// ---------------------------------------------------------------------------
__global__ void __launch_bounds__(256) k_gather(const int* __restrict__ edge,
                                                const float* __restrict__ gamma,
                                                const float* __restrict__ beta) {
    __shared__ float shsum[CO], shq[CO];
    __shared__ int s_last;
    int tid = threadIdx.x;
    int lane = tid & 31;
    int w = tid >> 5;
    if (tid < CO) { shsum[tid] = 0.f; shq[tid] = 0.f; }

    int bn0 = blockIdx.x * 64;
    int b = bn0 / NN;
    size_t zb = (size_t)b*NN*CO;

    float accs0 = 0.f, accs1 = 0.f, accq0 = 0.f, accq1 = 0.f;

    for (int it = 0; it < 8; it++) {
        int bn = bn0 + w*8 + it;
        size_t base = (size_t)bn*CO;
        float y0 = g_yT[base + lane];
        float y1 = g_yT[base + lane + 32];
        int myidx = edge[bn*KK + (lane & 15)];
        float s10 = 0.f, s11 = 0.f, q0 = 0.f, q1 = 0.f;
        float mn0 = CUDART_INF_F, mn1 = CUDART_INF_F;
        float mx0 = -CUDART_INF_F, mx1 = -CUDART_INF_F;
        #pragma unroll
        for (int k = 0; k < KK; k++) {
            int e = __shfl_sync(0xffffffffu, myidx, k);
            size_t zr = zb + (size_t)e*CO;
            float z0 = g_zT[zr + lane];
            float z1 = g_zT[zr + lane + 32];
            s10 += z0; q0 = fmaf(z0, z0, q0);
            mn0 = fminf(mn0, z0); mx0 = fmaxf(mx0, z0);
            s11 += z1; q1 = fmaf(z1, z1, q1);
            mn1 = fminf(mn1, z1); mx1 = fmaxf(mx1, z1);
        }
        g_hmax[base + lane]      = y0 - mn0;
        g_hmax[base + lane + 32] = y1 - mn1;
        g_hmin[base + lane]      = y0 - mx0;
        g_hmin[base + lane + 32] = y1 - mx1;
        accs0 += (float)KK*y0 - s10;
        accs1 += (float)KK*y1 - s11;
        accq0 += fmaf((float)KK*y0, y0, fmaf(-2.f*y0, s10, q0));
        accq1 += fmaf((float)KK*y1, y1, fmaf(-2.f*y1, s11, q1));
    }
    __syncthreads();
    atomicAdd(&shsum[lane],      accs0);
    atomicAdd(&shsum[lane + 32], accs1);
    atomicAdd(&shq[lane],        accq0);
    atomicAdd(&shq[lane + 32],   accq1);
    __syncthreads();
    if (tid < CO) {
        atomicAdd(&g_sum[tid],   shsum[tid]);
        atomicAdd(&g_sumsq[tid], shq[tid]);
    }
    __threadfence();
    __syncthreads();
    if (tid == 0) s_last = (atomicAdd(&g_ticket, 1) == (int)gridDim.x - 1);
    __syncthreads();
    if (s_last && tid < CO) {
        const float inv = 1.0f / (float)((long long)BB*NN*KK);
        float sm = atomicAdd(&g_sum[tid],   0.f);
        float sq = atomicAdd(&g_sumsq[tid], 0.f);
        float mean = sm * inv;
        float var  = sq * inv - mean*mean;
        float s = gamma[tid] * rsqrtf(var + 1e-5f);
        g_scale[tid] = s;
        g_shift[tid] = beta[tid] - mean * s;
    }
}

// ---------------------------------------------------------------------------
// Kernel C: epilogue + transpose to output layout (B, CO, N).
// max_k leaky(s*h+t) = leaky(s*hext + t), hext = hmax if s>=0 else hmin.
// ---------------------------------------------------------------------------
__global__ void __launch_bounds__(256) k_out(float* __restrict__ out) {
    __shared__ float tile[64*65];
    __shared__ float ss[CO], tt[CO];
    int tid = threadIdx.x;
    if (tid < CO) { ss[tid] = g_scale[tid]; tt[tid] = g_shift[tid]; }
    __syncthreads();
    int b = blockIdx.y;
    int n0 = blockIdx.x * 64;
    size_t base = ((size_t)b*NN + n0)*CO;
    for (int i = tid; i < 64*64; i += 256) {
        int nl = i >> 6, o = i & 63;
        float s = ss[o];
        const float* src = (s >= 0.f) ? g_hmax : g_hmin;
        float v = src[base + (size_t)nl*CO + o];
        float h = fmaf(s, v, tt[o]);
        tile[o*65 + nl] = (h >= 0.f) ? h : 0.2f*h;
    }
    __syncthreads();
    size_t ob = (size_t)b*CO*NN + n0;
    for (int i = tid; i < 64*64; i += 256) {
        int o = i >> 6, nl = i & 63;
        out[ob + (size_t)o*NN + nl] = tile[o*65 + nl];
    }
}

extern "C" void kernel_launch(void* const* d_in, const int* in_sizes, int n_in,
                              void* d_out, int out_size) {
    const float* x     = (const float*)d_in[0];
    const int*   edge  = (const int*)d_in[1];
    const float* W     = (const float*)d_in[2];
    const float* gamma = (const float*)d_in[3];
    const float* beta  = (const float*)d_in[4];
    float* out = (float*)d_out;

    k_gemm<<<BB*NN/64, 256>>>(x, W);
    k_gather<<<BB*NN/64, 256>>>(edge, gamma, beta);
    k_out<<<dim3(NN/64, BB), 256>>>(out);
}